// round 15
// baseline (speedup 1.0000x reference)
#include <cuda_runtime.h>
#include <cuda_fp16.h>
#include <cstdint>

#define NB   4
#define CIN  32
#define CC   64
#define V3   32768
#define NG   8
#define EPS  1e-5f

__device__ __align__(16) float g_pts[NB * CC * V3];
__device__ __align__(16) float g_vox_a[NB * V3 * CC];
__device__ __align__(16) float g_vox_b[NB * V3 * CC];
__device__ __align__(16) __half g_hi[NB * V3 * CC];
__device__ __align__(16) unsigned char g_wblob[442368];  // [conv][tap][64x128B sw128] hi only
__device__ int   g_cnt[NB * V3];
__device__ float g_bias[NB * CC];
__device__ float g_sac[128];
__device__ float g_qac[128];

__device__ __forceinline__ float siluf(float x) { return x / (1.f + __expf(-x)); }

__device__ __forceinline__ float2 murs(const float* __restrict__ sac,
                                       const float* __restrict__ qac, int bg) {
    float m = sac[bg] * (1.f / 262144.f);
    float v = qac[bg] * (1.f / 262144.f) - m * m;
    return make_float2(m, rsqrtf(v + EPS));
}

__device__ __forceinline__ uint32_t s2u(const void* p) {
    uint32_t a;
    asm("{ .reg .u64 t; cvta.to.shared.u64 t, %1; cvt.u32.u64 %0, t; }" : "=r"(a) : "l"(p));
    return a;
}

#define LDSM4(R, addr) \
    asm volatile("ldmatrix.sync.aligned.m8n8.x4.shared.b16 {%0,%1,%2,%3}, [%4];" \
        : "=r"((R)[0]), "=r"((R)[1]), "=r"((R)[2]), "=r"((R)[3]) : "r"(addr))
#define LDSM4T(r0, r1, r2, r3, addr) \
    asm volatile("ldmatrix.sync.aligned.m8n8.x4.trans.shared.b16 {%0,%1,%2,%3}, [%4];" \
        : "=r"(r0), "=r"(r1), "=r"(r2), "=r"(r3) : "r"(addr))
#define MMA(dacc, A, B) \
    asm volatile("mma.sync.aligned.m16n8k16.row.col.f32.f16.f16.f32 " \
        "{%0,%1,%2,%3}, {%4,%5,%6,%7}, {%8,%9}, {%0,%1,%2,%3};" \
        : "+f"((dacc)[0]), "+f"((dacc)[1]), "+f"((dacc)[2]), "+f"((dacc)[3]) \
        : "r"((A)[0]), "r"((A)[1]), "r"((A)[2]), "r"((A)[3]), "r"((B)[0]), "r"((B)[1]))

__device__ __forceinline__ void cp16(uint32_t dst, const void* src) {
    asm volatile("cp.async.cg.shared.global [%0], [%1], 16;" :: "r"(dst), "l"(src));
}
__device__ __forceinline__ void cp16z(uint32_t dst, const void* src, bool ok) {
    int sz = ok ? 16 : 0;
    asm volatile("cp.async.cg.shared.global [%0], [%1], 16, %2;" :: "r"(dst), "l"(src), "r"(sz));
}
#define CP_COMMIT() asm volatile("cp.async.commit_group;" ::: "memory")
#define CP_WAIT(n)  asm volatile("cp.async.wait_group %0;" :: "n"(n) : "memory")

// ---------------- small kernels ----------------
__global__ void k_bias(const float* __restrict__ te_, const float* __restrict__ wt,
                       const float* __restrict__ bt) {
    __shared__ float te[256];
    int b = blockIdx.x, o = threadIdx.x;
    for (int i = o; i < 256; i += 64) te[i] = te_[b * 256 + i];
    __syncthreads();
    float s = bt[o];
    #pragma unroll 8
    for (int t = 0; t < 256; t++) s += te[t] * wt[o * 256 + t];
    g_bias[b * CC + o] = s;
}

// pw_in: 2 points x 32 oc per thread; fused GN1 stats
__global__ void __launch_bounds__(256) k_pw_in(const float* __restrict__ f,
                                               const float* __restrict__ w,
                                               float* __restrict__ sac, float* __restrict__ qac) {
    __shared__ float sw[CIN * CC];
    __shared__ float sx[CIN * 256];
    __shared__ float rsm[8][4], rqm[8][4];
    int tid = threadIdx.x;
    int n0 = (blockIdx.x & 127) << 8;
    int b = blockIdx.x >> 7;
    for (int i = tid; i < CIN * CC; i += 256) sw[(i & 31) * CC + (i >> 5)] = w[i];
    for (int i = tid; i < 2048; i += 256) {
        int c = i >> 6, pt4 = i & 63;
        float4 v = *(const float4*)(f + ((b * CIN + c) << 15) + n0 + pt4 * 4);
        *(float4*)(sx + c * 256 + pt4 * 4) = v;
    }
    __syncthreads();
    int half = tid >> 7;
    int pl = tid & 127;
    int n = n0 + pl * 2;
    int o0 = half << 5;
    float acc[2][32];
    #pragma unroll
    for (int o = 0; o < 32; o++) { acc[0][o] = 0.f; acc[1][o] = 0.f; }
    for (int c = 0; c < CIN; c++) {
        float2 x = *(const float2*)(sx + c * 256 + pl * 2);
        const float4* wr = (const float4*)(sw + c * CC + o0);
        #pragma unroll
        for (int q = 0; q < 8; q++) {
            float4 ww = wr[q];
            acc[0][q*4+0] += x.x*ww.x; acc[0][q*4+1] += x.x*ww.y;
            acc[0][q*4+2] += x.x*ww.z; acc[0][q*4+3] += x.x*ww.w;
            acc[1][q*4+0] += x.y*ww.x; acc[1][q*4+1] += x.y*ww.y;
            acc[1][q*4+2] += x.y*ww.z; acc[1][q*4+3] += x.y*ww.w;
        }
    }
    #pragma unroll
    for (int o = 0; o < 32; o++)
        *(float2*)(g_pts + ((b * CC + o0 + o) << 15) + n) = make_float2(acc[0][o], acc[1][o]);
    float s4[4], q4[4];
    #pragma unroll
    for (int g = 0; g < 4; g++) {
        float s = 0.f, q = 0.f;
        #pragma unroll
        for (int j = 0; j < 8; j++) {
            float v0 = acc[0][g*8+j], v1 = acc[1][g*8+j];
            s += v0 + v1; q += v0*v0 + v1*v1;
        }
        s4[g] = s; q4[g] = q;
    }
    #pragma unroll
    for (int off = 16; off > 0; off >>= 1)
        #pragma unroll
        for (int g = 0; g < 4; g++) {
            s4[g] += __shfl_down_sync(0xffffffffu, s4[g], off);
            q4[g] += __shfl_down_sync(0xffffffffu, q4[g], off);
        }
    int wid = tid >> 5, lane = tid & 31;
    if (lane == 0) {
        #pragma unroll
        for (int g = 0; g < 4; g++) { rsm[wid][g] = s4[g]; rqm[wid][g] = q4[g]; }
    }
    __syncthreads();
    if (tid < 8) {
        int w0 = (tid < 4) ? 0 : 4, gl = tid & 3;
        float s = rsm[w0][gl] + rsm[w0+1][gl] + rsm[w0+2][gl] + rsm[w0+3][gl];
        float q = rqm[w0][gl] + rqm[w0+1][gl] + rqm[w0+2][gl] + rqm[w0+3][gl];
        atomicAdd(sac + b * 8 + tid, s);
        atomicAdd(qac + b * 8 + tid, q);
    }
}

__global__ void k_zero() {
    int t = blockIdx.x * 256 + threadIdx.x;
    float4 z = make_float4(0.f, 0.f, 0.f, 0.f);
    float4* p = (float4*)g_vox_a;
    p[t] = z; p[t + 524288] = z; p[t + 1048576] = z; p[t + 1572864] = z;
    if (t < 32768) ((int4*)g_cnt)[t] = make_int4(0, 0, 0, 0);
    if (t < 128) { g_sac[t] = 0.f; g_qac[t] = 0.f; }
}

// scatter: GN1 (inline finalize) + SiLU + bias, scatter-add
__global__ void __launch_bounds__(128) k_scatter(const float* __restrict__ coords,
                                                 const float* __restrict__ gg,
                                                 const float* __restrict__ gb,
                                                 const float* __restrict__ sac,
                                                 const float* __restrict__ qac) {
    int p = blockIdx.x * 128 + threadIdx.x;
    int b = p >> 15, n = p & 32767;
    float mu8[8], rs8[8];
    #pragma unroll
    for (int g = 0; g < 8; g++) {
        float2 mr = murs(sac, qac, b * 8 + g);
        mu8[g] = mr.x; rs8[g] = mr.y;
    }
    int ix = min(max(__float2int_rd(coords[p*3+0]*31.f), 0), 31);
    int iy = min(max(__float2int_rd(coords[p*3+1]*31.f), 0), 31);
    int iz = min(max(__float2int_rd(coords[p*3+2]*31.f), 0), 31);
    int flat = (ix << 10) + (iy << 5) + iz;
    atomicAdd(&g_cnt[(b << 15) + flat], 1);
    float* dst = g_vox_a + ((size_t)((b << 15) + flat) << 6);
    #pragma unroll 4
    for (int c = 0; c < CC; c++) {
        int g = c >> 3;
        float x = g_pts[((b * CC + c) << 15) + n];
        x = siluf((x - mu8[g]) * rs8[g] * gg[c] + gb[c]) + g_bias[b * CC + c];
        atomicAdd(dst + c, x);
    }
}

__global__ void k_voxfin_cvt() {
    int idx = blockIdx.x * 256 + threadIdx.x;
    int b = idx >> 15;
    float inv = 1.f / (float)max(g_cnt[idx], 1);
    const float4* s4 = (const float4*)(g_vox_a + ((size_t)idx << 6));
    uint4* h4 = (uint4*)(g_hi + ((size_t)idx << 6));
    const float* bias = g_bias + b * CC;
    #pragma unroll
    for (int q = 0; q < 8; q++) {
        float4 v0 = s4[q*2], v1 = s4[q*2+1];
        float x[8] = {v0.x,v0.y,v0.z,v0.w,v1.x,v1.y,v1.z,v1.w};
        unsigned short hs[8];
        #pragma unroll
        for (int j = 0; j < 8; j++)
            hs[j] = __half_as_ushort(__float2half_rn(x[j]*inv + bias[q*8+j]));
        h4[q] = make_uint4(hs[0]|((uint32_t)hs[1]<<16), hs[2]|((uint32_t)hs[3]<<16),
                           hs[4]|((uint32_t)hs[5]<<16), hs[6]|((uint32_t)hs[7]<<16));
    }
}

// GN + SiLU + fp16 convert into g_hi
__global__ void k_gnsilu_cvt(const float* __restrict__ src,
                             const float* __restrict__ gg, const float* __restrict__ gb,
                             const float* __restrict__ sac, const float* __restrict__ qac) {
    int idx = blockIdx.x * 256 + threadIdx.x;
    int b = idx >> 15;
    const float4* s4 = (const float4*)(src + ((size_t)idx << 6));
    uint4* h4 = (uint4*)(g_hi + ((size_t)idx << 6));
    #pragma unroll
    for (int q = 0; q < 8; q++) {
        float2 mr = murs(sac, qac, b * NG + q);
        float4 v0 = s4[q*2], v1 = s4[q*2+1];
        float x[8] = {v0.x,v0.y,v0.z,v0.w,v1.x,v1.y,v1.z,v1.w};
        unsigned short hs[8];
        #pragma unroll
        for (int j = 0; j < 8; j++) {
            int c = q*8+j;
            hs[j] = __half_as_ushort(__float2half_rn(siluf((x[j]-mr.x)*mr.y*gg[c] + gb[c])));
        }
        h4[q] = make_uint4(hs[0]|((uint32_t)hs[1]<<16), hs[2]|((uint32_t)hs[3]<<16),
                           hs[4]|((uint32_t)hs[5]<<16), hs[6]|((uint32_t)hs[7]<<16));
    }
}

// wblob: B matrix per tap (hi only): row k = c_in (64 x 128B), col n = o_out, SW128.
__global__ void k_wprep(const float* __restrict__ w1, const float* __restrict__ w2) {
    int i = blockIdx.x * 256 + threadIdx.x;
    if (i >= 221184) return;
    int conv = i / 110592, r = i - conv * 110592;
    int o = r / 1728, r2 = r - o * 1728;
    int c = r2 / 27, t = r2 - c * 27;
    float w = conv ? w2[r] : w1[r];
    __half h = __float2half_rn(w);
    uint32_t off = (uint32_t)c * 128 + (uint32_t)o * 2;
    uint32_t swo = off ^ ((off >> 3) & 0x70);
    *(__half*)(g_wblob + (size_t)conv * 221184 + (size_t)t * 8192 + swo) = h;
}

// ---------------- HMMA conv: slab-batched staging, 2 syncs/slab, 2 CTAs/SM ----------------
// smem: A [0, 26112); W taps [26112 + t9*8192), t9 = 0..8  => 99840 B
#define CONV_SMEM 99840

__global__ void __launch_bounds__(256, 2)
k_conv_mma(const __half* __restrict__ hi,
           const unsigned char* __restrict__ wblob, float* __restrict__ out,
           float* __restrict__ sac, float* __restrict__ qac) {
    extern __shared__ char smem[];
    const uint32_t sb = s2u(smem);
    const int tid = threadIdx.x, wid = tid >> 5, lane = tid & 31;
    int t = blockIdx.x;
    int b = t >> 8, tt = t & 255;
    int d = tt >> 3, h0 = (tt & 7) << 2;
    int r0 = t << 7;

    float acc[8][4];
    #pragma unroll
    for (int nt = 0; nt < 8; nt++)
        #pragma unroll
        for (int k = 0; k < 4; k++) acc[nt][k] = 0.f;

    const int a_r  = lane & 15;
    const int a_cb = (lane >> 4) << 4;

    for (int dz = 0; dz < 3; dz++) {
        int dp = d + dz - 1;
        if ((unsigned)dp >= 32u) continue;
        __syncthreads();                    // prior slab fully consumed
        // stage A slab (1632 x 16B, zfill OOB)
        for (int i = tid; i < 1632; i += 256) {
            int row = i >> 3, c16 = i & 7;
            int yyl = row / 34, xl = row - yyl * 34;
            int hh = h0 + yyl - 1, ww = xl - 1;
            bool ok = ((unsigned)hh < 32u) && ((unsigned)ww < 32u);
            size_t g = ok ? (((size_t)((b << 15) + (dp << 10) + (hh << 5) + ww) << 3) + c16) : 0;
            uint32_t doff = (uint32_t)row * 128 + ((c16 << 4) ^ ((row & 7) << 4));
            cp16z(sb + doff, (const uint4*)hi + g, ok);
        }
        // stage all 9 W taps (4608 x 16B)
        {
            const unsigned char* wsl = wblob + (size_t)(dz * 9) * 8192;
            #pragma unroll
            for (int k = 0; k < 18; k++) {
                int j = (tid << 4) + (k << 12);    // tid*16 + k*4096 bytes
                cp16(sb + 26112 + j, wsl + j);
            }
        }
        CP_COMMIT();
        CP_WAIT(0);
        __syncthreads();
        // 9 taps, barrier-free
        for (int t9 = 0; t9 < 9; t9++) {
            uint32_t wbase = sb + 26112 + (uint32_t)t9 * 8192;
            int dy = t9 / 3 - 1, dx = t9 - (t9 / 3) * 3 - 1;
            int srow_base = ((wid >> 1) + dy + 1) * 34 + ((wid & 1) << 4) + dx + 1;
            #pragma unroll
            for (int ks = 0; ks < 4; ks++) {
                uint32_t Ah[4], Bh[8][2];
                {
                    int row = srow_base + a_r;
                    uint32_t sw = (uint32_t)(((ks << 5) + a_cb) ^ ((row & 7) << 4));
                    LDSM4(Ah, sb + (uint32_t)row * 128 + sw);
                }
                {
                    int krow = (ks << 4) + (lane & 15);
                    uint32_t rbase = wbase + (uint32_t)krow * 128;
                    uint32_t xr = (uint32_t)((krow & 7) << 4);
                    int nbl = (lane >> 4) << 4;
                    #pragma unroll
                    for (int nt4 = 0; nt4 < 4; nt4++) {
                        uint32_t nb = (uint32_t)((nt4 << 5) + nbl);
                        uint32_t addr = rbase + (nb ^ xr);
                        LDSM4T(Bh[nt4*2][0], Bh[nt4*2][1], Bh[nt4*2+1][0], Bh[nt4*2+1][1], addr);
                    }
                }
                #pragma unroll
                for (int nt = 0; nt < 8; nt++)
                    MMA(acc[nt], Ah, Bh[nt]);
            }
        }
    }
    // fused stats
    __syncthreads();
    {
        float s8[8], q8[8];
        #pragma unroll
        for (int nt = 0; nt < 8; nt++) {
            s8[nt] = acc[nt][0] + acc[nt][1] + acc[nt][2] + acc[nt][3];
            q8[nt] = acc[nt][0]*acc[nt][0] + acc[nt][1]*acc[nt][1]
                   + acc[nt][2]*acc[nt][2] + acc[nt][3]*acc[nt][3];
        }
        #pragma unroll
        for (int off = 16; off > 0; off >>= 1)
            #pragma unroll
            for (int g = 0; g < 8; g++) {
                s8[g] += __shfl_down_sync(0xffffffffu, s8[g], off);
                q8[g] += __shfl_down_sync(0xffffffffu, q8[g], off);
            }
        float* rsm = (float*)(smem + 26112);
        if (lane == 0) {
            #pragma unroll
            for (int g = 0; g < 8; g++) { rsm[wid*16+g] = s8[g]; rsm[wid*16+8+g] = q8[g]; }
        }
        __syncthreads();
        if (tid < 16) {
            float tsum = 0.f;
            #pragma unroll
            for (int w = 0; w < 8; w++) tsum += rsm[w*16+tid];
            if (tid < 8) atomicAdd(sac + b * 8 + tid, tsum);
            else         atomicAdd(qac + b * 8 + (tid - 8), tsum);
        }
    }
    // epilogue
    int g = lane >> 2, tg = lane & 3;
    int v0 = r0 + (wid << 4) + g;
    #pragma unroll
    for (int nt = 0; nt < 8; nt++) {
        int c = (nt << 3) + tg * 2;
        float* o = out + ((size_t)v0 << 6) + c;
        o[0] = acc[nt][0];
        o[1] = acc[nt][1];
        o[512] = acc[nt][2];
        o[513] = acc[nt][3];
    }
}

// ---------------- devox + fuse: fp16 voxel gather, fused GN4 stats ----------------
__global__ void __launch_bounds__(256) k_devox(const float* __restrict__ coords,
                                               const float* __restrict__ wfuse,
                                               float* __restrict__ sac, float* __restrict__ qac) {
    __shared__ float swf[CC * CC];
    __shared__ float rsm[8][4], rqm[8][4];
    int tid = threadIdx.x;
    for (int i = tid; i < CC * CC; i += 256) swf[(i & 63) * CC + (i >> 6)] = wfuse[i];
    __syncthreads();
    int half = tid >> 7;
    int p = blockIdx.x * 128 + (tid & 127);
    int b = p >> 15, n = p & 32767;
    int o0 = half << 5;
    float cx = coords[p*3+0]*31.f, cy = coords[p*3+1]*31.f, cz = coords[p*3+2]*31.f;
    float fx = cx - floorf(cx), fy = cy - floorf(cy), fz = cz - floorf(cz);
    int x0 = min(max(__float2int_rd(cx),0),31), x1 = min(x0+1,31);
    int y0 = min(max(__float2int_rd(cy),0),31), y1 = min(y0+1,31);
    int z0 = min(max(__float2int_rd(cz),0),31), z1 = min(z0+1,31);
    const uint2* base[8]; float wk[8]; int k = 0;
    #pragma unroll
    for (int ddx = 0; ddx < 2; ddx++)
        #pragma unroll
        for (int ddy = 0; ddy < 2; ddy++)
            #pragma unroll
            for (int ddz = 0; ddz < 2; ddz++) {
                int X = ddx?x1:x0, Y = ddy?y1:y0, Z = ddz?z1:z0;
                wk[k] = (ddx?fx:1.f-fx)*(ddy?fy:1.f-fy)*(ddz?fz:1.f-fz);
                base[k] = (const uint2*)(g_hi + (((size_t)(b<<15) + ((X<<10)+(Y<<5)+Z)) << 6));
                k++;
            }
    float acc[32];
    #pragma unroll
    for (int o = 0; o < 32; o++) acc[o] = 0.f;
    #pragma unroll
    for (int c4 = 0; c4 < 16; c4++) {
        float r[32];
        #pragma unroll
        for (int kk = 0; kk < 8; kk++) {
            uint2 u = __ldg(base[kk] + c4);
            float2 fa = __half22float2(*(__half2*)&u.x);
            float2 fb = __half22float2(*(__half2*)&u.y);
            r[kk*4] = fa.x; r[kk*4+1] = fa.y; r[kk*4+2] = fb.x; r[kk*4+3] = fb.y;
        }
        #pragma unroll
        for (int j = 0; j < 4; j++) {
            float dd = r[j]*wk[0] + r[4+j]*wk[1] + r[8+j]*wk[2] + r[12+j]*wk[3]
                     + r[16+j]*wk[4] + r[20+j]*wk[5] + r[24+j]*wk[6] + r[28+j]*wk[7];
            const float4* wr = (const float4*)(swf + (c4*4+j)*CC + o0);
            #pragma unroll
            for (int q = 0; q < 8; q++) {
                float4 ww = wr[q];
                acc[q*4+0] += dd*ww.x; acc[q*4+1] += dd*ww.y; acc[q*4+2] += dd*ww.z; acc[q*4+3] += dd*ww.w;
            }
        }
    }
    #pragma unroll
    for (int o = 0; o < 32; o++) g_pts[((b * CC + o0 + o) << 15) + n] = acc[o];
    float s4[4], q4[4];
    #pragma unroll
    for (int g = 0; g < 4; g++) {
        float s = 0.f, q = 0.f;
        #pragma unroll
        for (int j = 0; j < 8; j++) { float v = acc[g*8+j]; s += v; q += v*v; }
        s4[g] = s; q4[g] = q;
    }
    #pragma unroll
    for (int off = 16; off > 0; off >>= 1)
        #pragma unroll
        for (int g = 0; g < 4; g++) {
            s4[g] += __shfl_down_sync(0xffffffffu, s4[g], off);
            q4[g] += __shfl_down_sync(0xffffffffu, q4[g], off);
        }
    int wid = tid >> 5, lane = tid & 31;
    if (lane == 0) {
        #pragma unroll
        for (int g = 0; g < 4; g++) { rsm[wid][g] = s4[g]; rqm[wid][g] = q4[g]; }
    }
    __syncthreads();
    if (tid < 8) {
        int w0 = (tid < 4) ? 0 : 4, gl = tid & 3;
        float s = rsm[w0][gl] + rsm[w0+1][gl] + rsm[w0+2][gl] + rsm[w0+3][gl];
        float q = rqm[w0][gl] + rqm[w0+1][gl] + rqm[w0+2][gl] + rqm[w0+3][gl];
        atomicAdd(sac + b * 8 + tid, s);
        atomicAdd(qac + b * 8 + tid, q);
    }
}

// final: 2 points x 32 oc per thread, feats staged in smem, GN4 inline finalize
__global__ void __launch_bounds__(256) k_final(const float* __restrict__ f,
                                               const float* __restrict__ wskip,
                                               const float* __restrict__ gg,
                                               const float* __restrict__ gb,
                                               const float* __restrict__ sac,
                                               const float* __restrict__ qac,
                                               float* __restrict__ out) {
    __shared__ float sw[CIN * CC];
    __shared__ float sx[CIN * 256];
    __shared__ float sg[64], sb2[64];
    int tid = threadIdx.x;
    int n0 = (blockIdx.x & 127) << 8;
    int b = blockIdx.x >> 7;
    for (int i = tid; i < CIN * CC; i += 256) sw[(i & 31) * CC + (i >> 5)] = wskip[i];
    for (int i = tid; i < 2048; i += 256) {
        int c = i >> 6, pt4 = i & 63;
        float4 v = *(const float4*)(f + ((b * CIN + c) << 15) + n0 + pt4 * 4);
        *(float4*)(sx + c * 256 + pt4 * 4) = v;
    }
    if (tid < 64) { sg[tid] = gg[tid]; sb2[tid] = gb[tid]; }
    __syncthreads();
    int half = tid >> 7;
    int pl = tid & 127;
    int n = n0 + pl * 2;
    int o0 = half << 5;
    float mu4[4], rs4[4];
    #pragma unroll
    for (int g = 0; g < 4; g++) {
        float2 mr = murs(sac, qac, b * 8 + (half << 2) + g);
        mu4[g] = mr.x; rs4[g] = mr.y;
    }
    float acc[2][32];
    #pragma unroll
    for (int o = 0; o < 32; o++) { acc[0][o] = 0.f; acc[1][o] = 0.f; }
    for (int c = 0; c < CIN; c++) {
        float2 x = *(const float2*)(sx + c * 256 + pl * 2);
        const float4* wr = (const float4*)(sw + c * CC + o0);
        #pragma unroll
        for (int q = 0; q < 8; q++) {
            float4 ww = wr[q];
            acc[0][q*4+0] += x.x*ww.x; acc[0][q*4+1] += x.x*ww.y;
            acc[0][q*4+2] += x.x*ww.z; acc[0][q*4+3] += x.x*ww.w;
            acc[1][q*4+0] += x.y*ww.x; acc[1][q*4+1] += x.y*ww.y;
            acc[1][q*4+2] += x.y*ww.z; acc[1][q*4+3] += x.y*ww.w;
        }
    }
    #pragma unroll
    for (int o = 0; o < 32; o++) {
        int oc = o0 + o;
        int g = o >> 3;
        float2 v = *(const float2*)(g_pts + ((b * CC + oc) << 15) + n);
        float r0 = (v.x - mu4[g]) * rs4[g] * sg[oc] + sb2[oc];
        float r1 = (v.y - mu4[g]) * rs4[g] * sg[oc] + sb2[oc];
        *(float2*)(out + ((b * CC + oc) << 15) + n) =
            make_float2(siluf(r0) + acc[0][o], siluf(r1) + acc[1][o]);
    }
}

// ---------------------------------------------------------------------------
extern "C" void kernel_launch(void* const* d_in, const int* in_sizes, int n_in,
                              void* d_out, int out_size) {
    const float* feats  = (const float*)d_in[0];
    const float* coords = (const float*)d_in[1];
    const float* t_emb  = (const float*)d_in[2];
    const float* w_in   = (const float*)d_in[3];
    const float* gn1_g  = (const float*)d_in[4];
    const float* gn1_b  = (const float*)d_in[5];
    const float* w_time = (const float*)d_in[6];
    const float* b_time = (const float*)d_in[7];
    const float* w_vox1 = (const float*)d_in[8];
    const float* gn2_g  = (const float*)d_in[9];
    const float* gn2_b  = (const float*)d_in[10];
    const float* w_vox2 = (const float*)d_in[11];
    const float* gn3_g  = (const float*)d_in[12];
    const float* gn3_b  = (const float*)d_in[13];
    const float* w_fuse = (const float*)d_in[14];
    const float* gn4_g  = (const float*)d_in[15];
    const float* gn4_b  = (const float*)d_in[16];
    const float* w_skip = (const float*)d_in[17];
    float* out = (float*)d_out;

    float *pts, *va, *vb, *sac, *qac;
    __half *hp;
    unsigned char* wb;
    cudaGetSymbolAddress((void**)&pts, g_pts);
    cudaGetSymbolAddress((void**)&va, g_vox_a);
    cudaGetSymbolAddress((void**)&vb, g_vox_b);
    cudaGetSymbolAddress((void**)&hp, g_hi);
    cudaGetSymbolAddress((void**)&wb, g_wblob);
    cudaGetSymbolAddress((void**)&sac, g_sac);
    cudaGetSymbolAddress((void**)&qac, g_qac);

    static int attr_set = 0;
    if (!attr_set) {
        cudaFuncSetAttribute(k_conv_mma, cudaFuncAttributeMaxDynamicSharedMemorySize, CONV_SMEM);
        attr_set = 1;
    }

    k_zero<<<2048, 256>>>();
    k_bias<<<NB, 64>>>(t_emb, w_time, b_time);
    k_wprep<<<864, 256>>>(w_vox1, w_vox2);
    k_pw_in<<<512, 256>>>(feats, w_in, sac, qac);
    k_scatter<<<1024, 128>>>(coords, gn1_g, gn1_b, sac, qac);
    k_voxfin_cvt<<<512, 256>>>();
    k_conv_mma<<<1024, 256, CONV_SMEM>>>(hp, wb, va, sac + 32, qac + 32);
    k_gnsilu_cvt<<<512, 256>>>(va, gn2_g, gn2_b, sac + 32, qac + 32);
    k_conv_mma<<<1024, 256, CONV_SMEM>>>(hp, wb + 221184, vb, sac + 64, qac + 64);
    k_gnsilu_cvt<<<512, 256>>>(vb, gn3_g, gn3_b, sac + 64, qac + 64);
    k_devox<<<1024, 256>>>(coords, w_fuse, sac + 96, qac + 96);
    k_final<<<512, 256>>>(feats, w_skip, gn4_g, gn4_b, sac + 96, qac + 96, out);
}

// round 16
// speedup vs baseline: 1.0952x; 1.0952x over previous
#include <cuda_runtime.h>
#include <cuda_fp16.h>
#include <cstdint>

#define NB   4
#define CIN  32
#define CC   64
#define V3   32768
#define NG   8
#define EPS  1e-5f

__device__ __align__(16) float g_pts[NB * CC * V3];
__device__ __align__(16) float g_vox_a[NB * V3 * CC];
__device__ __align__(16) float g_vox_b[NB * V3 * CC];
__device__ __align__(16) __half g_hi[NB * V3 * CC];
__device__ __align__(16) unsigned char g_wblob[442368];  // [conv][tap][64x128B sw128] hi only
__device__ int   g_cnt[NB * V3];
__device__ float g_bias[NB * CC];
__device__ float g_sac[128];
__device__ float g_qac[128];

__device__ __forceinline__ float siluf(float x) { return x / (1.f + __expf(-x)); }

__device__ __forceinline__ float2 murs(const float* __restrict__ sac,
                                       const float* __restrict__ qac, int bg) {
    float m = sac[bg] * (1.f / 262144.f);
    float v = qac[bg] * (1.f / 262144.f) - m * m;
    return make_float2(m, rsqrtf(v + EPS));
}

__device__ __forceinline__ uint32_t s2u(const void* p) {
    uint32_t a;
    asm("{ .reg .u64 t; cvta.to.shared.u64 t, %1; cvt.u32.u64 %0, t; }" : "=r"(a) : "l"(p));
    return a;
}

#define LDSM4(R, addr) \
    asm volatile("ldmatrix.sync.aligned.m8n8.x4.shared.b16 {%0,%1,%2,%3}, [%4];" \
        : "=r"((R)[0]), "=r"((R)[1]), "=r"((R)[2]), "=r"((R)[3]) : "r"(addr))
#define LDSM4T(r0, r1, r2, r3, addr) \
    asm volatile("ldmatrix.sync.aligned.m8n8.x4.trans.shared.b16 {%0,%1,%2,%3}, [%4];" \
        : "=r"(r0), "=r"(r1), "=r"(r2), "=r"(r3) : "r"(addr))
#define MMA(dacc, A, B) \
    asm volatile("mma.sync.aligned.m16n8k16.row.col.f32.f16.f16.f32 " \
        "{%0,%1,%2,%3}, {%4,%5,%6,%7}, {%8,%9}, {%0,%1,%2,%3};" \
        : "+f"((dacc)[0]), "+f"((dacc)[1]), "+f"((dacc)[2]), "+f"((dacc)[3]) \
        : "r"((A)[0]), "r"((A)[1]), "r"((A)[2]), "r"((A)[3]), "r"((B)[0]), "r"((B)[1]))

__device__ __forceinline__ void cp16(uint32_t dst, const void* src) {
    asm volatile("cp.async.cg.shared.global [%0], [%1], 16;" :: "r"(dst), "l"(src));
}
__device__ __forceinline__ void cp16z(uint32_t dst, const void* src, bool ok) {
    int sz = ok ? 16 : 0;
    asm volatile("cp.async.cg.shared.global [%0], [%1], 16, %2;" :: "r"(dst), "l"(src), "r"(sz));
}
#define CP_COMMIT() asm volatile("cp.async.commit_group;" ::: "memory")
#define CP_WAIT(n)  asm volatile("cp.async.wait_group %0;" :: "n"(n) : "memory")

__device__ __forceinline__ void red4(float* p, float a, float b, float c, float d) {
    asm volatile("red.global.add.v4.f32 [%0], {%1, %2, %3, %4};"
                 :: "l"(p), "f"(a), "f"(b), "f"(c), "f"(d) : "memory");
}

// ---------------- small kernels ----------------
__global__ void k_bias(const float* __restrict__ te_, const float* __restrict__ wt,
                       const float* __restrict__ bt) {
    __shared__ float te[256];
    int b = blockIdx.x, o = threadIdx.x;
    for (int i = o; i < 256; i += 64) te[i] = te_[b * 256 + i];
    __syncthreads();
    float s = bt[o];
    #pragma unroll 8
    for (int t = 0; t < 256; t++) s += te[t] * wt[o * 256 + t];
    g_bias[b * CC + o] = s;
}

// pw_in: 2 points x 32 oc per thread; fused GN1 stats
__global__ void __launch_bounds__(256) k_pw_in(const float* __restrict__ f,
                                               const float* __restrict__ w,
                                               float* __restrict__ sac, float* __restrict__ qac) {
    __shared__ float sw[CIN * CC];
    __shared__ float sx[CIN * 256];
    __shared__ float rsm[8][4], rqm[8][4];
    int tid = threadIdx.x;
    int n0 = (blockIdx.x & 127) << 8;
    int b = blockIdx.x >> 7;
    for (int i = tid; i < CIN * CC; i += 256) sw[(i & 31) * CC + (i >> 5)] = w[i];
    for (int i = tid; i < 2048; i += 256) {
        int c = i >> 6, pt4 = i & 63;
        float4 v = *(const float4*)(f + ((b * CIN + c) << 15) + n0 + pt4 * 4);
        *(float4*)(sx + c * 256 + pt4 * 4) = v;
    }
    __syncthreads();
    int half = tid >> 7;
    int pl = tid & 127;
    int n = n0 + pl * 2;
    int o0 = half << 5;
    float acc[2][32];
    #pragma unroll
    for (int o = 0; o < 32; o++) { acc[0][o] = 0.f; acc[1][o] = 0.f; }
    for (int c = 0; c < CIN; c++) {
        float2 x = *(const float2*)(sx + c * 256 + pl * 2);
        const float4* wr = (const float4*)(sw + c * CC + o0);
        #pragma unroll
        for (int q = 0; q < 8; q++) {
            float4 ww = wr[q];
            acc[0][q*4+0] += x.x*ww.x; acc[0][q*4+1] += x.x*ww.y;
            acc[0][q*4+2] += x.x*ww.z; acc[0][q*4+3] += x.x*ww.w;
            acc[1][q*4+0] += x.y*ww.x; acc[1][q*4+1] += x.y*ww.y;
            acc[1][q*4+2] += x.y*ww.z; acc[1][q*4+3] += x.y*ww.w;
        }
    }
    #pragma unroll
    for (int o = 0; o < 32; o++)
        *(float2*)(g_pts + ((b * CC + o0 + o) << 15) + n) = make_float2(acc[0][o], acc[1][o]);
    float s4[4], q4[4];
    #pragma unroll
    for (int g = 0; g < 4; g++) {
        float s = 0.f, q = 0.f;
        #pragma unroll
        for (int j = 0; j < 8; j++) {
            float v0 = acc[0][g*8+j], v1 = acc[1][g*8+j];
            s += v0 + v1; q += v0*v0 + v1*v1;
        }
        s4[g] = s; q4[g] = q;
    }
    #pragma unroll
    for (int off = 16; off > 0; off >>= 1)
        #pragma unroll
        for (int g = 0; g < 4; g++) {
            s4[g] += __shfl_down_sync(0xffffffffu, s4[g], off);
            q4[g] += __shfl_down_sync(0xffffffffu, q4[g], off);
        }
    int wid = tid >> 5, lane = tid & 31;
    if (lane == 0) {
        #pragma unroll
        for (int g = 0; g < 4; g++) { rsm[wid][g] = s4[g]; rqm[wid][g] = q4[g]; }
    }
    __syncthreads();
    if (tid < 8) {
        int w0 = (tid < 4) ? 0 : 4, gl = tid & 3;
        float s = rsm[w0][gl] + rsm[w0+1][gl] + rsm[w0+2][gl] + rsm[w0+3][gl];
        float q = rqm[w0][gl] + rqm[w0+1][gl] + rqm[w0+2][gl] + rqm[w0+3][gl];
        atomicAdd(sac + b * 8 + tid, s);
        atomicAdd(qac + b * 8 + tid, q);
    }
}

__global__ void k_zero() {
    int t = blockIdx.x * 256 + threadIdx.x;
    float4 z = make_float4(0.f, 0.f, 0.f, 0.f);
    float4* p = (float4*)g_vox_a;
    p[t] = z; p[t + 524288] = z; p[t + 1048576] = z; p[t + 1572864] = z;
    if (t < 32768) ((int4*)g_cnt)[t] = make_int4(0, 0, 0, 0);
    if (t < 128) { g_sac[t] = 0.f; g_qac[t] = 0.f; }
}

// scatter: GN1 (inline finalize) + SiLU + bias, vector red scatter-add
__global__ void __launch_bounds__(128) k_scatter(const float* __restrict__ coords,
                                                 const float* __restrict__ gg,
                                                 const float* __restrict__ gb,
                                                 const float* __restrict__ sac,
                                                 const float* __restrict__ qac) {
    int p = blockIdx.x * 128 + threadIdx.x;
    int b = p >> 15, n = p & 32767;
    float mu8[8], rs8[8];
    #pragma unroll
    for (int g = 0; g < 8; g++) {
        float2 mr = murs(sac, qac, b * 8 + g);
        mu8[g] = mr.x; rs8[g] = mr.y;
    }
    int ix = min(max(__float2int_rd(coords[p*3+0]*31.f), 0), 31);
    int iy = min(max(__float2int_rd(coords[p*3+1]*31.f), 0), 31);
    int iz = min(max(__float2int_rd(coords[p*3+2]*31.f), 0), 31);
    int flat = (ix << 10) + (iy << 5) + iz;
    atomicAdd(&g_cnt[(b << 15) + flat], 1);
    float* dst = g_vox_a + ((size_t)((b << 15) + flat) << 6);
    #pragma unroll 4
    for (int c = 0; c < CC; c += 4) {
        int g = c >> 3;
        float v[4];
        #pragma unroll
        for (int j = 0; j < 4; j++) {
            float x = g_pts[((b * CC + c + j) << 15) + n];
            v[j] = siluf((x - mu8[g]) * rs8[g] * gg[c+j] + gb[c+j]) + g_bias[b * CC + c + j];
        }
        red4(dst + c, v[0], v[1], v[2], v[3]);
    }
}

__global__ void k_voxfin_cvt() {
    int idx = blockIdx.x * 256 + threadIdx.x;
    int b = idx >> 15;
    float inv = 1.f / (float)max(g_cnt[idx], 1);
    const float4* s4 = (const float4*)(g_vox_a + ((size_t)idx << 6));
    uint4* h4 = (uint4*)(g_hi + ((size_t)idx << 6));
    const float* bias = g_bias + b * CC;
    #pragma unroll
    for (int q = 0; q < 8; q++) {
        float4 v0 = s4[q*2], v1 = s4[q*2+1];
        float x[8] = {v0.x,v0.y,v0.z,v0.w,v1.x,v1.y,v1.z,v1.w};
        unsigned short hs[8];
        #pragma unroll
        for (int j = 0; j < 8; j++)
            hs[j] = __half_as_ushort(__float2half_rn(x[j]*inv + bias[q*8+j]));
        h4[q] = make_uint4(hs[0]|((uint32_t)hs[1]<<16), hs[2]|((uint32_t)hs[3]<<16),
                           hs[4]|((uint32_t)hs[5]<<16), hs[6]|((uint32_t)hs[7]<<16));
    }
}

// GN + SiLU + fp16 convert into g_hi
__global__ void k_gnsilu_cvt(const float* __restrict__ src,
                             const float* __restrict__ gg, const float* __restrict__ gb,
                             const float* __restrict__ sac, const float* __restrict__ qac) {
    int idx = blockIdx.x * 256 + threadIdx.x;
    int b = idx >> 15;
    const float4* s4 = (const float4*)(src + ((size_t)idx << 6));
    uint4* h4 = (uint4*)(g_hi + ((size_t)idx << 6));
    #pragma unroll
    for (int q = 0; q < 8; q++) {
        float2 mr = murs(sac, qac, b * NG + q);
        float4 v0 = s4[q*2], v1 = s4[q*2+1];
        float x[8] = {v0.x,v0.y,v0.z,v0.w,v1.x,v1.y,v1.z,v1.w};
        unsigned short hs[8];
        #pragma unroll
        for (int j = 0; j < 8; j++) {
            int c = q*8+j;
            hs[j] = __half_as_ushort(__float2half_rn(siluf((x[j]-mr.x)*mr.y*gg[c] + gb[c])));
        }
        h4[q] = make_uint4(hs[0]|((uint32_t)hs[1]<<16), hs[2]|((uint32_t)hs[3]<<16),
                           hs[4]|((uint32_t)hs[5]<<16), hs[6]|((uint32_t)hs[7]<<16));
    }
}

// wblob: B matrix per tap (hi only): row k = c_in (64 x 128B), col n = o_out, SW128.
__global__ void k_wprep(const float* __restrict__ w1, const float* __restrict__ w2) {
    int i = blockIdx.x * 256 + threadIdx.x;
    if (i >= 221184) return;
    int conv = i / 110592, r = i - conv * 110592;
    int o = r / 1728, r2 = r - o * 1728;
    int c = r2 / 27, t = r2 - c * 27;
    float w = conv ? w2[r] : w1[r];
    __half h = __float2half_rn(w);
    uint32_t off = (uint32_t)c * 128 + (uint32_t)o * 2;
    uint32_t swo = off ^ ((off >> 3) & 0x70);
    *(__half*)(g_wblob + (size_t)conv * 221184 + (size_t)t * 8192 + swo) = h;
}

// ---------------- HMMA conv: M=32 x N=32 per warp, slab-batched staging ----------------
// smem: A [0, 26112); W taps [26112 + t9*8192), t9 = 0..8  => 99840 B
#define CONV_SMEM 99840

__global__ void __launch_bounds__(256, 2)
k_conv_mma(const __half* __restrict__ hi,
           const unsigned char* __restrict__ wblob, float* __restrict__ out,
           float* __restrict__ sac, float* __restrict__ qac) {
    extern __shared__ char smem[];
    const uint32_t sb = s2u(smem);
    const int tid = threadIdx.x, wid = tid >> 5, lane = tid & 31;
    int t = blockIdx.x;
    int b = t >> 8, tt = t & 255;
    int d = tt >> 3, h0 = (tt & 7) << 2;
    int r0 = t << 7;
    const int mw = wid >> 1, nw = wid & 1;

    float acc[2][4][4];
    #pragma unroll
    for (int mt = 0; mt < 2; mt++)
        #pragma unroll
        for (int nt = 0; nt < 4; nt++)
            #pragma unroll
            for (int k = 0; k < 4; k++) acc[mt][nt][k] = 0.f;

    const int a_r  = lane & 15;
    const int a_cb = (lane >> 4) << 4;

    for (int dz = 0; dz < 3; dz++) {
        int dp = d + dz - 1;
        if ((unsigned)dp >= 32u) continue;
        __syncthreads();
        for (int i = tid; i < 1632; i += 256) {
            int row = i >> 3, c16 = i & 7;
            int yyl = row / 34, xl = row - yyl * 34;
            int hh = h0 + yyl - 1, ww = xl - 1;
            bool ok = ((unsigned)hh < 32u) && ((unsigned)ww < 32u);
            size_t g = ok ? (((size_t)((b << 15) + (dp << 10) + (hh << 5) + ww) << 3) + c16) : 0;
            uint32_t doff = (uint32_t)row * 128 + ((c16 << 4) ^ ((row & 7) << 4));
            cp16z(sb + doff, (const uint4*)hi + g, ok);
        }
        {
            const unsigned char* wsl = wblob + (size_t)(dz * 9) * 8192;
            #pragma unroll
            for (int k = 0; k < 18; k++) {
                int j = (tid << 4) + (k << 12);
                cp16(sb + 26112 + j, wsl + j);
            }
        }
        CP_COMMIT();
        CP_WAIT(0);
        __syncthreads();
        for (int t9 = 0; t9 < 9; t9++) {
            uint32_t wbase = sb + 26112 + (uint32_t)t9 * 8192;
            int dy = t9 / 3 - 1, dx = t9 - (t9 / 3) * 3 - 1;
            int srow_base = (mw + dy + 1) * 34 + dx + 1;
            #pragma unroll
            for (int ks = 0; ks < 4; ks++) {
                uint32_t Ah[2][4], Bh[4][2];
                #pragma unroll
                for (int mt = 0; mt < 2; mt++) {
                    int row = srow_base + (mt << 4) + a_r;
                    uint32_t sw = (uint32_t)(((ks << 5) + a_cb) ^ ((row & 7) << 4));
                    LDSM4(Ah[mt], sb + (uint32_t)row * 128 + sw);
                }
                {
                    int krow = (ks << 4) + (lane & 15);
                    uint32_t rbase = wbase + (uint32_t)krow * 128;
                    uint32_t xr = (uint32_t)((krow & 7) << 4);
                    int nbl = (lane >> 4) << 4;
                    #pragma unroll
                    for (int nt4 = 0; nt4 < 2; nt4++) {
                        uint32_t nb = (uint32_t)((nw << 6) + (nt4 << 5) + nbl);
                        uint32_t addr = rbase + (nb ^ xr);
                        LDSM4T(Bh[nt4*2][0], Bh[nt4*2][1], Bh[nt4*2+1][0], Bh[nt4*2+1][1], addr);
                    }
                }
                #pragma unroll
                for (int mt = 0; mt < 2; mt++)
                    #pragma unroll
                    for (int nt = 0; nt < 4; nt++)
                        MMA(acc[mt][nt], Ah[mt], Bh[nt]);
            }
        }
    }
    // fused stats: thread's acc[.][nt] belongs to group nw*4 + nt
    __syncthreads();
    {
        float s4[4], q4[4];
        #pragma unroll
        for (int nt = 0; nt < 4; nt++) {
            float s = 0.f, q = 0.f;
            #pragma unroll
            for (int mt = 0; mt < 2; mt++)
                #pragma unroll
                for (int k = 0; k < 4; k++) { float v = acc[mt][nt][k]; s += v; q += v*v; }
            s4[nt] = s; q4[nt] = q;
        }
        #pragma unroll
        for (int off = 16; off > 0; off >>= 1)
            #pragma unroll
            for (int g = 0; g < 4; g++) {
                s4[g] += __shfl_down_sync(0xffffffffu, s4[g], off);
                q4[g] += __shfl_down_sync(0xffffffffu, q4[g], off);
            }
        float* rsm = (float*)(smem + 26112);
        if (lane == 0) {
            #pragma unroll
            for (int g = 0; g < 4; g++) { rsm[wid*8+g] = s4[g]; rsm[wid*8+4+g] = q4[g]; }
        }
        __syncthreads();
        if (tid < 16) {
            int G = tid & 7;
            int nws = G >> 2, g4 = G & 3;
            int base = (tid < 8) ? g4 : (4 + g4);       // sum vs sumsq slot
            float tsum = rsm[nws*8 + base] + rsm[(nws+2)*8 + base]
                       + rsm[(nws+4)*8 + base] + rsm[(nws+6)*8 + base];
            if (tid < 8) atomicAdd(sac + b * 8 + G, tsum);
            else         atomicAdd(qac + b * 8 + G, tsum);
        }
    }
    // epilogue
    int g = lane >> 2, tg = lane & 3;
    #pragma unroll
    for (int mt = 0; mt < 2; mt++) {
        int v0 = r0 + (mw << 5) + (mt << 4) + g;
        #pragma unroll
        for (int nt = 0; nt < 4; nt++) {
            int c = (nw << 5) + (nt << 3) + tg * 2;
            float* o = out + ((size_t)v0 << 6) + c;
            o[0] = acc[mt][nt][0];
            o[1] = acc[mt][nt][1];
            o[512] = acc[mt][nt][2];
            o[513] = acc[mt][nt][3];
        }
    }
}

// ---------------- devox + fuse: fp16 voxel gather, fused GN4 stats ----------------
__global__ void __launch_bounds__(256) k_devox(const float* __restrict__ coords,
                                               const float* __restrict__ wfuse,
                                               float* __restrict__ sac, float* __restrict__ qac) {
    __shared__ float swf[CC * CC];
    __shared__ float rsm[8][4], rqm[8][4];
    int tid = threadIdx.x;
    for (int i = tid; i < CC * CC; i += 256) swf[(i & 63) * CC + (i >> 6)] = wfuse[i];
    __syncthreads();
    int half = tid >> 7;
    int p = blockIdx.x * 128 + (tid & 127);
    int b = p >> 15, n = p & 32767;
    int o0 = half << 5;
    float cx = coords[p*3+0]*31.f, cy = coords[p*3+1]*31.f, cz = coords[p*3+2]*31.f;
    float fx = cx - floorf(cx), fy = cy - floorf(cy), fz = cz - floorf(cz);
    int x0 = min(max(__float2int_rd(cx),0),31), x1 = min(x0+1,31);
    int y0 = min(max(__float2int_rd(cy),0),31), y1 = min(y0+1,31);
    int z0 = min(max(__float2int_rd(cz),0),31), z1 = min(z0+1,31);
    const uint2* base[8]; float wk[8]; int k = 0;
    #pragma unroll
    for (int ddx = 0; ddx < 2; ddx++)
        #pragma unroll
        for (int ddy = 0; ddy < 2; ddy++)
            #pragma unroll
            for (int ddz = 0; ddz < 2; ddz++) {
                int X = ddx?x1:x0, Y = ddy?y1:y0, Z = ddz?z1:z0;
                wk[k] = (ddx?fx:1.f-fx)*(ddy?fy:1.f-fy)*(ddz?fz:1.f-fz);
                base[k] = (const uint2*)(g_hi + (((size_t)(b<<15) + ((X<<10)+(Y<<5)+Z)) << 6));
                k++;
            }
    float acc[32];
    #pragma unroll
    for (int o = 0; o < 32; o++) acc[o] = 0.f;
    #pragma unroll
    for (int c4 = 0; c4 < 16; c4++) {
        float r[32];
        #pragma unroll
        for (int kk = 0; kk < 8; kk++) {
            uint2 u = __ldg(base[kk] + c4);
            float2 fa = __half22float2(*(__half2*)&u.x);
            float2 fb = __half22float2(*(__half2*)&u.y);
            r[kk*4] = fa.x; r[kk*4+1] = fa.y; r[kk*4+2] = fb.x; r[kk*4+3] = fb.y;
        }
        #pragma unroll
        for (int j = 0; j < 4; j++) {
            float dd = r[j]*wk[0] + r[4+j]*wk[1] + r[8+j]*wk[2] + r[12+j]*wk[3]
                     + r[16+j]*wk[4] + r[20+j]*wk[5] + r[24+j]*wk[6] + r[28+j]*wk[7];
            const float4* wr = (const float4*)(swf + (c4*4+j)*CC + o0);
            #pragma unroll
            for (int q = 0; q < 8; q++) {
                float4 ww = wr[q];
                acc[q*4+0] += dd*ww.x; acc[q*4+1] += dd*ww.y; acc[q*4+2] += dd*ww.z; acc[q*4+3] += dd*ww.w;
            }
        }
    }
    #pragma unroll
    for (int o = 0; o < 32; o++) g_pts[((b * CC + o0 + o) << 15) + n] = acc[o];
    float s4[4], q4[4];
    #pragma unroll
    for (int g = 0; g < 4; g++) {
        float s = 0.f, q = 0.f;
        #pragma unroll
        for (int j = 0; j < 8; j++) { float v = acc[g*8+j]; s += v; q += v*v; }
        s4[g] = s; q4[g] = q;
    }
    #pragma unroll
    for (int off = 16; off > 0; off >>= 1)
        #pragma unroll
        for (int g = 0; g < 4; g++) {
            s4[g] += __shfl_down_sync(0xffffffffu, s4[g], off);
            q4[g] += __shfl_down_sync(0xffffffffu, q4[g], off);
        }
    int wid = tid >> 5, lane = tid & 31;
    if (lane == 0) {
        #pragma unroll
        for (int g = 0; g < 4; g++) { rsm[wid][g] = s4[g]; rqm[wid][g] = q4[g]; }
    }
    __syncthreads();
    if (tid < 8) {
        int w0 = (tid < 4) ? 0 : 4, gl = tid & 3;
        float s = rsm[w0][gl] + rsm[w0+1][gl] + rsm[w0+2][gl] + rsm[w0+3][gl];
        float q = rqm[w0][gl] + rqm[w0+1][gl] + rqm[w0+2][gl] + rqm[w0+3][gl];
        atomicAdd(sac + b * 8 + tid, s);
        atomicAdd(qac + b * 8 + tid, q);
    }
}

// final: 2 points x 32 oc per thread, feats staged in smem, GN4 inline finalize
__global__ void __launch_bounds__(256) k_final(const float* __restrict__ f,
                                               const float* __restrict__ wskip,
                                               const float* __restrict__ gg,
                                               const float* __restrict__ gb,
                                               const float* __restrict__ sac,
                                               const float* __restrict__ qac,
                                               float* __restrict__ out) {
    __shared__ float sw[CIN * CC];
    __shared__ float sx[CIN * 256];
    __shared__ float sg[64], sb2[64];
    int tid = threadIdx.x;
    int n0 = (blockIdx.x & 127) << 8;
    int b = blockIdx.x >> 7;
    for (int i = tid; i < CIN * CC; i += 256) sw[(i & 31) * CC + (i >> 5)] = wskip[i];
    for (int i = tid; i < 2048; i += 256) {
        int c = i >> 6, pt4 = i & 63;
        float4 v = *(const float4*)(f + ((b * CIN + c) << 15) + n0 + pt4 * 4);
        *(float4*)(sx + c * 256 + pt4 * 4) = v;
    }
    if (tid < 64) { sg[tid] = gg[tid]; sb2[tid] = gb[tid]; }
    __syncthreads();
    int half = tid >> 7;
    int pl = tid & 127;
    int n = n0 + pl * 2;
    int o0 = half << 5;
    float mu4[4], rs4[4];
    #pragma unroll
    for (int g = 0; g < 4; g++) {
        float2 mr = murs(sac, qac, b * 8 + (half << 2) + g);
        mu4[g] = mr.x; rs4[g] = mr.y;
    }
    float acc[2][32];
    #pragma unroll
    for (int o = 0; o < 32; o++) { acc[0][o] = 0.f; acc[1][o] = 0.f; }
    for (int c = 0; c < CIN; c++) {
        float2 x = *(const float2*)(sx + c * 256 + pl * 2);
        const float4* wr = (const float4*)(sw + c * CC + o0);
        #pragma unroll
        for (int q = 0; q < 8; q++) {
            float4 ww = wr[q];
            acc[0][q*4+0] += x.x*ww.x; acc[0][q*4+1] += x.x*ww.y;
            acc[0][q*4+2] += x.x*ww.z; acc[0][q*4+3] += x.x*ww.w;
            acc[1][q*4+0] += x.y*ww.x; acc[1][q*4+1] += x.y*ww.y;
            acc[1][q*4+2] += x.y*ww.z; acc[1][q*4+3] += x.y*ww.w;
        }
    }
    #pragma unroll
    for (int o = 0; o < 32; o++) {
        int oc = o0 + o;
        int g = o >> 3;
        float2 v = *(const float2*)(g_pts + ((b * CC + oc) << 15) + n);
        float r0 = (v.x - mu4[g]) * rs4[g] * sg[oc] + sb2[oc];
        float r1 = (v.y - mu4[g]) * rs4[g] * sg[oc] + sb2[oc];
        *(float2*)(out + ((b * CC + oc) << 15) + n) =
            make_float2(siluf(r0) + acc[0][o], siluf(r1) + acc[1][o]);
    }
}

// ---------------------------------------------------------------------------
extern "C" void kernel_launch(void* const* d_in, const int* in_sizes, int n_in,
                              void* d_out, int out_size) {
    const float* feats  = (const float*)d_in[0];
    const float* coords = (const float*)d_in[1];
    const float* t_emb  = (const float*)d_in[2];
    const float* w_in   = (const float*)d_in[3];
    const float* gn1_g  = (const float*)d_in[4];
    const float* gn1_b  = (const float*)d_in[5];
    const float* w_time = (const float*)d_in[6];
    const float* b_time = (const float*)d_in[7];
    const float* w_vox1 = (const float*)d_in[8];
    const float* gn2_g  = (const float*)d_in[9];
    const float* gn2_b  = (const float*)d_in[10];
    const float* w_vox2 = (const float*)d_in[11];
    const float* gn3_g  = (const float*)d_in[12];
    const float* gn3_b  = (const float*)d_in[13];
    const float* w_fuse = (const float*)d_in[14];
    const float* gn4_g  = (const float*)d_in[15];
    const float* gn4_b  = (const float*)d_in[16];
    const float* w_skip = (const float*)d_in[17];
    float* out = (float*)d_out;

    float *pts, *va, *vb, *sac, *qac;
    __half *hp;
    unsigned char* wb;
    cudaGetSymbolAddress((void**)&pts, g_pts);
    cudaGetSymbolAddress((void**)&va, g_vox_a);
    cudaGetSymbolAddress((void**)&vb, g_vox_b);
    cudaGetSymbolAddress((void**)&hp, g_hi);
    cudaGetSymbolAddress((void**)&wb, g_wblob);
    cudaGetSymbolAddress((void**)&sac, g_sac);
    cudaGetSymbolAddress((void**)&qac, g_qac);

    static int attr_set = 0;
    if (!attr_set) {
        cudaFuncSetAttribute(k_conv_mma, cudaFuncAttributeMaxDynamicSharedMemorySize, CONV_SMEM);
        attr_set = 1;
    }

    k_zero<<<2048, 256>>>();
    k_bias<<<NB, 64>>>(t_emb, w_time, b_time);
    k_wprep<<<864, 256>>>(w_vox1, w_vox2);
    k_pw_in<<<512, 256>>>(feats, w_in, sac, qac);
    k_scatter<<<1024, 128>>>(coords, gn1_g, gn1_b, sac, qac);
    k_voxfin_cvt<<<512, 256>>>();
    k_conv_mma<<<1024, 256, CONV_SMEM>>>(hp, wb, va, sac + 32, qac + 32);
    k_gnsilu_cvt<<<512, 256>>>(va, gn2_g, gn2_b, sac + 32, qac + 32);
    k_conv_mma<<<1024, 256, CONV_SMEM>>>(hp, wb + 221184, vb, sac + 64, qac + 64);
    k_gnsilu_cvt<<<512, 256>>>(vb, gn3_g, gn3_b, sac + 64, qac + 64);
    k_devox<<<1024, 256>>>(coords, w_fuse, sac + 96, qac + 96);
    k_final<<<512, 256>>>(feats, w_skip, gn4_g, gn4_b, sac + 96, qac + 96, out);
}

// round 17
// speedup vs baseline: 1.1125x; 1.0158x over previous
#include <cuda_runtime.h>
#include <cuda_fp16.h>
#include <cstdint>

#define NB   4
#define CIN  32
#define CC   64
#define V3   32768
#define NG   8
#define EPS  1e-5f

__device__ __align__(16) float g_pts[NB * CC * V3];
__device__ __align__(16) float g_vox_a[NB * V3 * CC];
__device__ __align__(16) float g_vox_b[NB * V3 * CC];
__device__ __align__(16) __half g_hi[NB * V3 * CC];
__device__ __align__(16) unsigned char g_wblob[442368];  // [conv][tap][64x128B sw128] hi only
__device__ int   g_cnt[NB * V3];
__device__ float g_bias[NB * CC];
__device__ float g_sac[128];
__device__ float g_qac[128];

__device__ __forceinline__ float siluf(float x) { return x / (1.f + __expf(-x)); }

__device__ __forceinline__ float2 murs(const float* __restrict__ sac,
                                       const float* __restrict__ qac, int bg) {
    float m = sac[bg] * (1.f / 262144.f);
    float v = qac[bg] * (1.f / 262144.f) - m * m;
    return make_float2(m, rsqrtf(v + EPS));
}

__device__ __forceinline__ uint32_t s2u(const void* p) {
    uint32_t a;
    asm("{ .reg .u64 t; cvta.to.shared.u64 t, %1; cvt.u32.u64 %0, t; }" : "=r"(a) : "l"(p));
    return a;
}

#define LDSM4(R, addr) \
    asm volatile("ldmatrix.sync.aligned.m8n8.x4.shared.b16 {%0,%1,%2,%3}, [%4];" \
        : "=r"((R)[0]), "=r"((R)[1]), "=r"((R)[2]), "=r"((R)[3]) : "r"(addr))
#define LDSM4T(r0, r1, r2, r3, addr) \
    asm volatile("ldmatrix.sync.aligned.m8n8.x4.trans.shared.b16 {%0,%1,%2,%3}, [%4];" \
        : "=r"(r0), "=r"(r1), "=r"(r2), "=r"(r3) : "r"(addr))
#define MMA(dacc, A, B) \
    asm volatile("mma.sync.aligned.m16n8k16.row.col.f32.f16.f16.f32 " \
        "{%0,%1,%2,%3}, {%4,%5,%6,%7}, {%8,%9}, {%0,%1,%2,%3};" \
        : "+f"((dacc)[0]), "+f"((dacc)[1]), "+f"((dacc)[2]), "+f"((dacc)[3]) \
        : "r"((A)[0]), "r"((A)[1]), "r"((A)[2]), "r"((A)[3]), "r"((B)[0]), "r"((B)[1]))

__device__ __forceinline__ void cp16(uint32_t dst, const void* src) {
    asm volatile("cp.async.cg.shared.global [%0], [%1], 16;" :: "r"(dst), "l"(src));
}
__device__ __forceinline__ void cp16z(uint32_t dst, const void* src, bool ok) {
    int sz = ok ? 16 : 0;
    asm volatile("cp.async.cg.shared.global [%0], [%1], 16, %2;" :: "r"(dst), "l"(src), "r"(sz));
}
#define CP_COMMIT() asm volatile("cp.async.commit_group;" ::: "memory")
#define CP_WAIT(n)  asm volatile("cp.async.wait_group %0;" :: "n"(n) : "memory")

__device__ __forceinline__ void red4(float* p, float a, float b, float c, float d) {
    asm volatile("red.global.add.v4.f32 [%0], {%1, %2, %3, %4};"
                 :: "l"(p), "f"(a), "f"(b), "f"(c), "f"(d) : "memory");
}

// ---------------- small kernels ----------------
__global__ void k_bias(const float* __restrict__ te_, const float* __restrict__ wt,
                       const float* __restrict__ bt) {
    __shared__ float te[256];
    int b = blockIdx.x, o = threadIdx.x;
    for (int i = o; i < 256; i += 64) te[i] = te_[b * 256 + i];
    __syncthreads();
    float s = bt[o];
    #pragma unroll 8
    for (int t = 0; t < 256; t++) s += te[t] * wt[o * 256 + t];
    g_bias[b * CC + o] = s;
}

// pw_in: 2 points x 32 oc per thread; fused GN1 stats
__global__ void __launch_bounds__(256) k_pw_in(const float* __restrict__ f,
                                               const float* __restrict__ w,
                                               float* __restrict__ sac, float* __restrict__ qac) {
    __shared__ float sw[CIN * CC];
    __shared__ float sx[CIN * 256];
    __shared__ float rsm[8][4], rqm[8][4];
    int tid = threadIdx.x;
    int n0 = (blockIdx.x & 127) << 8;
    int b = blockIdx.x >> 7;
    for (int i = tid; i < CIN * CC; i += 256) sw[(i & 31) * CC + (i >> 5)] = w[i];
    for (int i = tid; i < 2048; i += 256) {
        int c = i >> 6, pt4 = i & 63;
        float4 v = *(const float4*)(f + ((b * CIN + c) << 15) + n0 + pt4 * 4);
        *(float4*)(sx + c * 256 + pt4 * 4) = v;
    }
    __syncthreads();
    int half = tid >> 7;
    int pl = tid & 127;
    int n = n0 + pl * 2;
    int o0 = half << 5;
    float acc[2][32];
    #pragma unroll
    for (int o = 0; o < 32; o++) { acc[0][o] = 0.f; acc[1][o] = 0.f; }
    for (int c = 0; c < CIN; c++) {
        float2 x = *(const float2*)(sx + c * 256 + pl * 2);
        const float4* wr = (const float4*)(sw + c * CC + o0);
        #pragma unroll
        for (int q = 0; q < 8; q++) {
            float4 ww = wr[q];
            acc[0][q*4+0] += x.x*ww.x; acc[0][q*4+1] += x.x*ww.y;
            acc[0][q*4+2] += x.x*ww.z; acc[0][q*4+3] += x.x*ww.w;
            acc[1][q*4+0] += x.y*ww.x; acc[1][q*4+1] += x.y*ww.y;
            acc[1][q*4+2] += x.y*ww.z; acc[1][q*4+3] += x.y*ww.w;
        }
    }
    #pragma unroll
    for (int o = 0; o < 32; o++)
        *(float2*)(g_pts + ((b * CC + o0 + o) << 15) + n) = make_float2(acc[0][o], acc[1][o]);
    float s4[4], q4[4];
    #pragma unroll
    for (int g = 0; g < 4; g++) {
        float s = 0.f, q = 0.f;
        #pragma unroll
        for (int j = 0; j < 8; j++) {
            float v0 = acc[0][g*8+j], v1 = acc[1][g*8+j];
            s += v0 + v1; q += v0*v0 + v1*v1;
        }
        s4[g] = s; q4[g] = q;
    }
    #pragma unroll
    for (int off = 16; off > 0; off >>= 1)
        #pragma unroll
        for (int g = 0; g < 4; g++) {
            s4[g] += __shfl_down_sync(0xffffffffu, s4[g], off);
            q4[g] += __shfl_down_sync(0xffffffffu, q4[g], off);
        }
    int wid = tid >> 5, lane = tid & 31;
    if (lane == 0) {
        #pragma unroll
        for (int g = 0; g < 4; g++) { rsm[wid][g] = s4[g]; rqm[wid][g] = q4[g]; }
    }
    __syncthreads();
    if (tid < 8) {
        int w0 = (tid < 4) ? 0 : 4, gl = tid & 3;
        float s = rsm[w0][gl] + rsm[w0+1][gl] + rsm[w0+2][gl] + rsm[w0+3][gl];
        float q = rqm[w0][gl] + rqm[w0+1][gl] + rqm[w0+2][gl] + rqm[w0+3][gl];
        atomicAdd(sac + b * 8 + tid, s);
        atomicAdd(qac + b * 8 + tid, q);
    }
}

__global__ void k_zero() {
    int t = blockIdx.x * 256 + threadIdx.x;
    float4 z = make_float4(0.f, 0.f, 0.f, 0.f);
    float4* p = (float4*)g_vox_a;
    p[t] = z; p[t + 524288] = z; p[t + 1048576] = z; p[t + 1572864] = z;
    if (t < 32768) ((int4*)g_cnt)[t] = make_int4(0, 0, 0, 0);
    if (t < 128) { g_sac[t] = 0.f; g_qac[t] = 0.f; }
}

// scatter: GN1 (inline finalize) + SiLU + bias, vector red scatter-add
__global__ void __launch_bounds__(128) k_scatter(const float* __restrict__ coords,
                                                 const float* __restrict__ gg,
                                                 const float* __restrict__ gb,
                                                 const float* __restrict__ sac,
                                                 const float* __restrict__ qac) {
    int p = blockIdx.x * 128 + threadIdx.x;
    int b = p >> 15, n = p & 32767;
    float mu8[8], rs8[8];
    #pragma unroll
    for (int g = 0; g < 8; g++) {
        float2 mr = murs(sac, qac, b * 8 + g);
        mu8[g] = mr.x; rs8[g] = mr.y;
    }
    int ix = min(max(__float2int_rd(coords[p*3+0]*31.f), 0), 31);
    int iy = min(max(__float2int_rd(coords[p*3+1]*31.f), 0), 31);
    int iz = min(max(__float2int_rd(coords[p*3+2]*31.f), 0), 31);
    int flat = (ix << 10) + (iy << 5) + iz;
    atomicAdd(&g_cnt[(b << 15) + flat], 1);
    float* dst = g_vox_a + ((size_t)((b << 15) + flat) << 6);
    #pragma unroll 4
    for (int c = 0; c < CC; c += 4) {
        int g = c >> 3;
        float v[4];
        #pragma unroll
        for (int j = 0; j < 4; j++) {
            float x = g_pts[((b * CC + c + j) << 15) + n];
            v[j] = siluf((x - mu8[g]) * rs8[g] * gg[c+j] + gb[c+j]) + g_bias[b * CC + c + j];
        }
        red4(dst + c, v[0], v[1], v[2], v[3]);
    }
}

__global__ void k_voxfin_cvt() {
    int idx = blockIdx.x * 256 + threadIdx.x;
    int b = idx >> 15;
    float inv = 1.f / (float)max(g_cnt[idx], 1);
    const float4* s4 = (const float4*)(g_vox_a + ((size_t)idx << 6));
    uint4* h4 = (uint4*)(g_hi + ((size_t)idx << 6));
    const float* bias = g_bias + b * CC;
    #pragma unroll
    for (int q = 0; q < 8; q++) {
        float4 v0 = s4[q*2], v1 = s4[q*2+1];
        float x[8] = {v0.x,v0.y,v0.z,v0.w,v1.x,v1.y,v1.z,v1.w};
        unsigned short hs[8];
        #pragma unroll
        for (int j = 0; j < 8; j++)
            hs[j] = __half_as_ushort(__float2half_rn(x[j]*inv + bias[q*8+j]));
        h4[q] = make_uint4(hs[0]|((uint32_t)hs[1]<<16), hs[2]|((uint32_t)hs[3]<<16),
                           hs[4]|((uint32_t)hs[5]<<16), hs[6]|((uint32_t)hs[7]<<16));
    }
}

// GN + SiLU + fp16 convert into g_hi
__global__ void k_gnsilu_cvt(const float* __restrict__ src,
                             const float* __restrict__ gg, const float* __restrict__ gb,
                             const float* __restrict__ sac, const float* __restrict__ qac) {
    int idx = blockIdx.x * 256 + threadIdx.x;
    int b = idx >> 15;
    const float4* s4 = (const float4*)(src + ((size_t)idx << 6));
    uint4* h4 = (uint4*)(g_hi + ((size_t)idx << 6));
    #pragma unroll
    for (int q = 0; q < 8; q++) {
        float2 mr = murs(sac, qac, b * NG + q);
        float4 v0 = s4[q*2], v1 = s4[q*2+1];
        float x[8] = {v0.x,v0.y,v0.z,v0.w,v1.x,v1.y,v1.z,v1.w};
        unsigned short hs[8];
        #pragma unroll
        for (int j = 0; j < 8; j++) {
            int c = q*8+j;
            hs[j] = __half_as_ushort(__float2half_rn(siluf((x[j]-mr.x)*mr.y*gg[c] + gb[c])));
        }
        h4[q] = make_uint4(hs[0]|((uint32_t)hs[1]<<16), hs[2]|((uint32_t)hs[3]<<16),
                           hs[4]|((uint32_t)hs[5]<<16), hs[6]|((uint32_t)hs[7]<<16));
    }
}

// wblob: B matrix per tap (hi only): row k = c_in (64 x 128B), col n = o_out, SW128.
__global__ void k_wprep(const float* __restrict__ w1, const float* __restrict__ w2) {
    int i = blockIdx.x * 256 + threadIdx.x;
    if (i >= 221184) return;
    int conv = i / 110592, r = i - conv * 110592;
    int o = r / 1728, r2 = r - o * 1728;
    int c = r2 / 27, t = r2 - c * 27;
    float w = conv ? w2[r] : w1[r];
    __half h = __float2half_rn(w);
    uint32_t off = (uint32_t)c * 128 + (uint32_t)o * 2;
    uint32_t swo = off ^ ((off >> 3) & 0x70);
    *(__half*)(g_wblob + (size_t)conv * 221184 + (size_t)t * 8192 + swo) = h;
}

// ---------------- HMMA conv: M=32 x N=32 per warp, split W staging, 3 CTAs/SM ----------------
// smem: A [0, 26112); W slots [26112 + s*8192), s = 0..4  => 67072 B
#define CONV_SMEM 67072

__global__ void __launch_bounds__(256, 3)
k_conv_mma(const __half* __restrict__ hi,
           const unsigned char* __restrict__ wblob, float* __restrict__ out,
           float* __restrict__ sac, float* __restrict__ qac) {
    extern __shared__ char smem[];
    const uint32_t sb = s2u(smem);
    const int tid = threadIdx.x, wid = tid >> 5, lane = tid & 31;
    int t = blockIdx.x;
    int b = t >> 8, tt = t & 255;
    int d = tt >> 3, h0 = (tt & 7) << 2;
    int r0 = t << 7;
    const int mw = wid >> 1, nw = wid & 1;

    float acc[2][4][4];
    #pragma unroll
    for (int mt = 0; mt < 2; mt++)
        #pragma unroll
        for (int nt = 0; nt < 4; nt++)
            #pragma unroll
            for (int k = 0; k < 4; k++) acc[mt][nt][k] = 0.f;

    const int a_r  = lane & 15;
    const int a_cb = (lane >> 4) << 4;

    auto do_tap = [&](int t9, uint32_t wbase) {
        int dy = t9 / 3 - 1, dx = t9 - (t9 / 3) * 3 - 1;
        int srow_base = (mw + dy + 1) * 34 + dx + 1;
        #pragma unroll
        for (int ks = 0; ks < 4; ks++) {
            uint32_t Ah[2][4], Bh[4][2];
            #pragma unroll
            for (int mt = 0; mt < 2; mt++) {
                int row = srow_base + (mt << 4) + a_r;
                uint32_t sw = (uint32_t)(((ks << 5) + a_cb) ^ ((row & 7) << 4));
                LDSM4(Ah[mt], sb + (uint32_t)row * 128 + sw);
            }
            {
                int krow = (ks << 4) + (lane & 15);
                uint32_t rbase = wbase + (uint32_t)krow * 128;
                uint32_t xr = (uint32_t)((krow & 7) << 4);
                int nbl = (lane >> 4) << 4;
                #pragma unroll
                for (int nt4 = 0; nt4 < 2; nt4++) {
                    uint32_t nb = (uint32_t)((nw << 6) + (nt4 << 5) + nbl);
                    uint32_t addr = rbase + (nb ^ xr);
                    LDSM4T(Bh[nt4*2][0], Bh[nt4*2][1], Bh[nt4*2+1][0], Bh[nt4*2+1][1], addr);
                }
            }
            #pragma unroll
            for (int mt = 0; mt < 2; mt++)
                #pragma unroll
                for (int nt = 0; nt < 4; nt++)
                    MMA(acc[mt][nt], Ah[mt], Bh[nt]);
        }
    };

    for (int dz = 0; dz < 3; dz++) {
        int dp = d + dz - 1;
        if ((unsigned)dp >= 32u) continue;
        __syncthreads();                    // prior slab fully consumed
        // phase 1: stage A slab + W taps 0..4
        for (int i = tid; i < 1632; i += 256) {
            int row = i >> 3, c16 = i & 7;
            int yyl = row / 34, xl = row - yyl * 34;
            int hh = h0 + yyl - 1, ww = xl - 1;
            bool ok = ((unsigned)hh < 32u) && ((unsigned)ww < 32u);
            size_t g = ok ? (((size_t)((b << 15) + (dp << 10) + (hh << 5) + ww) << 3) + c16) : 0;
            uint32_t doff = (uint32_t)row * 128 + ((c16 << 4) ^ ((row & 7) << 4));
            cp16z(sb + doff, (const uint4*)hi + g, ok);
        }
        {
            const unsigned char* wsl = wblob + (size_t)(dz * 9) * 8192;
            #pragma unroll
            for (int k = 0; k < 10; k++) {      // 5 taps x 8KB = 2560 x 16B
                int j = (tid << 4) + (k << 12);
                cp16(sb + 26112 + j, wsl + j);
            }
        }
        CP_COMMIT();
        CP_WAIT(0);
        __syncthreads();
        for (int t9 = 0; t9 < 5; t9++) do_tap(t9, sb + 26112 + (uint32_t)t9 * 8192);
        __syncthreads();                    // slots 0..3 reuse guard
        // phase 2: stage W taps 5..8 into slots 0..3
        {
            const unsigned char* wsl = wblob + (size_t)(dz * 9 + 5) * 8192;
            #pragma unroll
            for (int k = 0; k < 8; k++) {       // 4 taps x 8KB = 2048 x 16B
                int j = (tid << 4) + (k << 12);
                cp16(sb + 26112 + j, wsl + j);
            }
        }
        CP_COMMIT();
        CP_WAIT(0);
        __syncthreads();
        for (int t9 = 5; t9 < 9; t9++) do_tap(t9, sb + 26112 + (uint32_t)(t9 - 5) * 8192);
    }
    // fused stats: thread's acc[.][nt] belongs to group nw*4 + nt
    __syncthreads();
    {
        float s4[4], q4[4];
        #pragma unroll
        for (int nt = 0; nt < 4; nt++) {
            float s = 0.f, q = 0.f;
            #pragma unroll
            for (int mt = 0; mt < 2; mt++)
                #pragma unroll
                for (int k = 0; k < 4; k++) { float v = acc[mt][nt][k]; s += v; q += v*v; }
            s4[nt] = s; q4[nt] = q;
        }
        #pragma unroll
        for (int off = 16; off > 0; off >>= 1)
            #pragma unroll
            for (int g = 0; g < 4; g++) {
                s4[g] += __shfl_down_sync(0xffffffffu, s4[g], off);
                q4[g] += __shfl_down_sync(0xffffffffu, q4[g], off);
            }
        float* rsm = (float*)(smem + 26112);
        if (lane == 0) {
            #pragma unroll
            for (int g = 0; g < 4; g++) { rsm[wid*8+g] = s4[g]; rsm[wid*8+4+g] = q4[g]; }
        }
        __syncthreads();
        if (tid < 16) {
            int G = tid & 7;
            int nws = G >> 2, g4 = G & 3;
            int base = (tid < 8) ? g4 : (4 + g4);
            float tsum = rsm[nws*8 + base] + rsm[(nws+2)*8 + base]
                       + rsm[(nws+4)*8 + base] + rsm[(nws+6)*8 + base];
            if (tid < 8) atomicAdd(sac + b * 8 + G, tsum);
            else         atomicAdd(qac + b * 8 + G, tsum);
        }
    }
    // epilogue
    int g = lane >> 2, tg = lane & 3;
    #pragma unroll
    for (int mt = 0; mt < 2; mt++) {
        int v0 = r0 + (mw << 5) + (mt << 4) + g;
        #pragma unroll
        for (int nt = 0; nt < 4; nt++) {
            int c = (nw << 5) + (nt << 3) + tg * 2;
            float* o = out + ((size_t)v0 << 6) + c;
            o[0] = acc[mt][nt][0];
            o[1] = acc[mt][nt][1];
            o[512] = acc[mt][nt][2];
            o[513] = acc[mt][nt][3];
        }
    }
}

// ---------------- devox + fuse: fp16 voxel gather, fused GN4 stats ----------------
__global__ void __launch_bounds__(256) k_devox(const float* __restrict__ coords,
                                               const float* __restrict__ wfuse,
                                               float* __restrict__ sac, float* __restrict__ qac) {
    __shared__ float swf[CC * CC];
    __shared__ float rsm[8][4], rqm[8][4];
    int tid = threadIdx.x;
    for (int i = tid; i < CC * CC; i += 256) swf[(i & 63) * CC + (i >> 6)] = wfuse[i];
    __syncthreads();
    int half = tid >> 7;
    int p = blockIdx.x * 128 + (tid & 127);
    int b = p >> 15, n = p & 32767;
    int o0 = half << 5;
    float cx = coords[p*3+0]*31.f, cy = coords[p*3+1]*31.f, cz = coords[p*3+2]*31.f;
    float fx = cx - floorf(cx), fy = cy - floorf(cy), fz = cz - floorf(cz);
    int x0 = min(max(__float2int_rd(cx),0),31), x1 = min(x0+1,31);
    int y0 = min(max(__float2int_rd(cy),0),31), y1 = min(y0+1,31);
    int z0 = min(max(__float2int_rd(cz),0),31), z1 = min(z0+1,31);
    const uint2* base[8]; float wk[8]; int k = 0;
    #pragma unroll
    for (int ddx = 0; ddx < 2; ddx++)
        #pragma unroll
        for (int ddy = 0; ddy < 2; ddy++)
            #pragma unroll
            for (int ddz = 0; ddz < 2; ddz++) {
                int X = ddx?x1:x0, Y = ddy?y1:y0, Z = ddz?z1:z0;
                wk[k] = (ddx?fx:1.f-fx)*(ddy?fy:1.f-fy)*(ddz?fz:1.f-fz);
                base[k] = (const uint2*)(g_hi + (((size_t)(b<<15) + ((X<<10)+(Y<<5)+Z)) << 6));
                k++;
            }
    float acc[32];
    #pragma unroll
    for (int o = 0; o < 32; o++) acc[o] = 0.f;
    #pragma unroll
    for (int c4 = 0; c4 < 16; c4++) {
        float r[32];
        #pragma unroll
        for (int kk = 0; kk < 8; kk++) {
            uint2 u = __ldg(base[kk] + c4);
            float2 fa = __half22float2(*(__half2*)&u.x);
            float2 fb = __half22float2(*(__half2*)&u.y);
            r[kk*4] = fa.x; r[kk*4+1] = fa.y; r[kk*4+2] = fb.x; r[kk*4+3] = fb.y;
        }
        #pragma unroll
        for (int j = 0; j < 4; j++) {
            float dd = r[j]*wk[0] + r[4+j]*wk[1] + r[8+j]*wk[2] + r[12+j]*wk[3]
                     + r[16+j]*wk[4] + r[20+j]*wk[5] + r[24+j]*wk[6] + r[28+j]*wk[7];
            const float4* wr = (const float4*)(swf + (c4*4+j)*CC + o0);
            #pragma unroll
            for (int q = 0; q < 8; q++) {
                float4 ww = wr[q];
                acc[q*4+0] += dd*ww.x; acc[q*4+1] += dd*ww.y; acc[q*4+2] += dd*ww.z; acc[q*4+3] += dd*ww.w;
            }
        }
    }
    #pragma unroll
    for (int o = 0; o < 32; o++) g_pts[((b * CC + o0 + o) << 15) + n] = acc[o];
    float s4[4], q4[4];
    #pragma unroll
    for (int g = 0; g < 4; g++) {
        float s = 0.f, q = 0.f;
        #pragma unroll
        for (int j = 0; j < 8; j++) { float v = acc[g*8+j]; s += v; q += v*v; }
        s4[g] = s; q4[g] = q;
    }
    #pragma unroll
    for (int off = 16; off > 0; off >>= 1)
        #pragma unroll
        for (int g = 0; g < 4; g++) {
            s4[g] += __shfl_down_sync(0xffffffffu, s4[g], off);
            q4[g] += __shfl_down_sync(0xffffffffu, q4[g], off);
        }
    int wid = tid >> 5, lane = tid & 31;
    if (lane == 0) {
        #pragma unroll
        for (int g = 0; g < 4; g++) { rsm[wid][g] = s4[g]; rqm[wid][g] = q4[g]; }
    }
    __syncthreads();
    if (tid < 8) {
        int w0 = (tid < 4) ? 0 : 4, gl = tid & 3;
        float s = rsm[w0][gl] + rsm[w0+1][gl] + rsm[w0+2][gl] + rsm[w0+3][gl];
        float q = rqm[w0][gl] + rqm[w0+1][gl] + rqm[w0+2][gl] + rqm[w0+3][gl];
        atomicAdd(sac + b * 8 + tid, s);
        atomicAdd(qac + b * 8 + tid, q);
    }
}

// final: 2 points x 32 oc per thread, feats staged in smem, GN4 inline finalize
__global__ void __launch_bounds__(256) k_final(const float* __restrict__ f,
                                               const float* __restrict__ wskip,
                                               const float* __restrict__ gg,
                                               const float* __restrict__ gb,
                                               const float* __restrict__ sac,
                                               const float* __restrict__ qac,
                                               float* __restrict__ out) {
    __shared__ float sw[CIN * CC];
    __shared__ float sx[CIN * 256];
    __shared__ float sg[64], sb2[64];
    int tid = threadIdx.x;
    int n0 = (blockIdx.x & 127) << 8;
    int b = blockIdx.x >> 7;
    for (int i = tid; i < CIN * CC; i += 256) sw[(i & 31) * CC + (i >> 5)] = wskip[i];
    for (int i = tid; i < 2048; i += 256) {
        int c = i >> 6, pt4 = i & 63;
        float4 v = *(const float4*)(f + ((b * CIN + c) << 15) + n0 + pt4 * 4);
        *(float4*)(sx + c * 256 + pt4 * 4) = v;
    }
    if (tid < 64) { sg[tid] = gg[tid]; sb2[tid] = gb[tid]; }
    __syncthreads();
    int half = tid >> 7;
    int pl = tid & 127;
    int n = n0 + pl * 2;
    int o0 = half << 5;
    float mu4[4], rs4[4];
    #pragma unroll
    for (int g = 0; g < 4; g++) {
        float2 mr = murs(sac, qac, b * 8 + (half << 2) + g);
        mu4[g] = mr.x; rs4[g] = mr.y;
    }
    float acc[2][32];
    #pragma unroll
    for (int o = 0; o < 32; o++) { acc[0][o] = 0.f; acc[1][o] = 0.f; }
    for (int c = 0; c < CIN; c++) {
        float2 x = *(const float2*)(sx + c * 256 + pl * 2);
        const float4* wr = (const float4*)(sw + c * CC + o0);
        #pragma unroll
        for (int q = 0; q < 8; q++) {
            float4 ww = wr[q];
            acc[0][q*4+0] += x.x*ww.x; acc[0][q*4+1] += x.x*ww.y;
            acc[0][q*4+2] += x.x*ww.z; acc[0][q*4+3] += x.x*ww.w;
            acc[1][q*4+0] += x.y*ww.x; acc[1][q*4+1] += x.y*ww.y;
            acc[1][q*4+2] += x.y*ww.z; acc[1][q*4+3] += x.y*ww.w;
        }
    }
    #pragma unroll
    for (int o = 0; o < 32; o++) {
        int oc = o0 + o;
        int g = o >> 3;
        float2 v = *(const float2*)(g_pts + ((b * CC + oc) << 15) + n);
        float r0 = (v.x - mu4[g]) * rs4[g] * sg[oc] + sb2[oc];
        float r1 = (v.y - mu4[g]) * rs4[g] * sg[oc] + sb2[oc];
        *(float2*)(out + ((b * CC + oc) << 15) + n) =
            make_float2(siluf(r0) + acc[0][o], siluf(r1) + acc[1][o]);
    }
}

// ---------------------------------------------------------------------------
extern "C" void kernel_launch(void* const* d_in, const int* in_sizes, int n_in,
                              void* d_out, int out_size) {
    const float* feats  = (const float*)d_in[0];
    const float* coords = (const float*)d_in[1];
    const float* t_emb  = (const float*)d_in[2];
    const float* w_in   = (const float*)d_in[3];
    const float* gn1_g  = (const float*)d_in[4];
    const float* gn1_b  = (const float*)d_in[5];
    const float* w_time = (const float*)d_in[6];
    const float* b_time = (const float*)d_in[7];
    const float* w_vox1 = (const float*)d_in[8];
    const float* gn2_g  = (const float*)d_in[9];
    const float* gn2_b  = (const float*)d_in[10];
    const float* w_vox2 = (const float*)d_in[11];
    const float* gn3_g  = (const float*)d_in[12];
    const float* gn3_b  = (const float*)d_in[13];
    const float* w_fuse = (const float*)d_in[14];
    const float* gn4_g  = (const float*)d_in[15];
    const float* gn4_b  = (const float*)d_in[16];
    const float* w_skip = (const float*)d_in[17];
    float* out = (float*)d_out;

    float *pts, *va, *vb, *sac, *qac;
    __half *hp;
    unsigned char* wb;
    cudaGetSymbolAddress((void**)&pts, g_pts);
    cudaGetSymbolAddress((void**)&va, g_vox_a);
    cudaGetSymbolAddress((void**)&vb, g_vox_b);
    cudaGetSymbolAddress((void**)&hp, g_hi);
    cudaGetSymbolAddress((void**)&wb, g_wblob);
    cudaGetSymbolAddress((void**)&sac, g_sac);
    cudaGetSymbolAddress((void**)&qac, g_qac);

    static int attr_set = 0;
    if (!attr_set) {
        cudaFuncSetAttribute(k_conv_mma, cudaFuncAttributeMaxDynamicSharedMemorySize, CONV_SMEM);
        attr_set = 1;
    }

    k_zero<<<2048, 256>>>();
    k_bias<<<NB, 64>>>(t_emb, w_time, b_time);
    k_wprep<<<864, 256>>>(w_vox1, w_vox2);
    k_pw_in<<<512, 256>>>(feats, w_in, sac, qac);
    k_scatter<<<1024, 128>>>(coords, gn1_g, gn1_b, sac, qac);
    k_voxfin_cvt<<<512, 256>>>();
    k_conv_mma<<<1024, 256, CONV_SMEM>>>(hp, wb, va, sac + 32, qac + 32);
    k_gnsilu_cvt<<<512, 256>>>(va, gn2_g, gn2_b, sac + 32, qac + 32);
    k_conv_mma<<<1024, 256, CONV_SMEM>>>(hp, wb + 221184, vb, sac + 64, qac + 64);
    k_gnsilu_cvt<<<512, 256>>>(vb, gn3_g, gn3_b, sac + 64, qac + 64);
    k_devox<<<1024, 256>>>(coords, w_fuse, sac + 96, qac + 96);
    k_final<<<512, 256>>>(feats, w_skip, gn4_g, gn4_b, sac + 96, qac + 96, out);
}